// round 1
// baseline (speedup 1.0000x reference)
#include <cuda_runtime.h>
#include <math.h>

#define SEQ   1024
#define MEMN  1024
#define TT    2048
#define BATCH 4
#define NH    16
#define DH    64
#define DM    1024
#define BH    (BATCH*NH)   // 64

// ---------------- scratch (device globals; no allocation allowed) ----------------
__device__ float g_qu[(size_t)BH*SEQ*DH];     // [b][h][i][d]  q + pos_bias_u
__device__ float g_qv[(size_t)BH*SEQ*DH];     // [b][h][i][d]  q + pos_bias_v
__device__ float g_k [(size_t)BH*TT*DH];      // [b][h][t][d]
__device__ float g_v [(size_t)BH*TT*DH];      // [b][h][t][d]
__device__ float g_r [(size_t)BH*TT*DH];      // [b][h][t][d]
__device__ float g_ac[(size_t)BH*SEQ*TT];     // [b][h][i][j]  AC scores -> exp'd probs (in place)
__device__ float g_bd[(size_t)BH*SEQ*TT];     // [b][h][i][e]  BD raw (pre-shift)
__device__ float g_sinv[(size_t)BH*SEQ];      // 1/sum per row
__device__ float g_av[(size_t)SEQ*BATCH*DM];  // attn_vec, rows = (i*B+b), cols = h*64+d

// ---------------- reductions ----------------
__device__ __forceinline__ float warpReduceSum(float v){
    #pragma unroll
    for (int o = 16; o > 0; o >>= 1) v += __shfl_xor_sync(0xffffffffu, v, o);
    return v;
}
__device__ __forceinline__ float warpReduceMax(float v){
    #pragma unroll
    for (int o = 16; o > 0; o >>= 1) v = fmaxf(v, __shfl_xor_sync(0xffffffffu, v, o));
    return v;
}

// ---------------- kernel 1: fused QKV + R projection GEMM ----------------
// out[m,n] = sum_k A[m,k] * W[n,k]
//   n in [0,3072):  A = concat(memory, x) row m, W = W_qkv
//   n in [3072,4096): A = pos_emb row m,     W = W_rel
// epilogue scatters into g_qu/g_qv (with bias), g_k, g_v, g_r
__global__ __launch_bounds__(256) void proj_kernel(
    const float* __restrict__ x, const float* __restrict__ mem,
    const float* __restrict__ pos, const float* __restrict__ Wqkv,
    const float* __restrict__ Wrel, const float* __restrict__ pbu,
    const float* __restrict__ pbv)
{
    __shared__ float As[8][128];
    __shared__ float Bs[8][128];
    const int bm = blockIdx.y * 128;
    const int bn = blockIdx.x * 128;
    const int tid = threadIdx.x;
    const int lr = tid >> 1;
    const int kq = (tid & 1) * 4;

    const int m = bm + lr;
    const float* arow;
    if (bn >= 3072) arow = pos + (size_t)m * DM;
    else arow = (m < MEMN*BATCH) ? (mem + (size_t)m * DM)
                                 : (x + (size_t)(m - MEMN*BATCH) * DM);
    const int nrow = bn + lr;
    const float* brow = (nrow < 3072) ? (Wqkv + (size_t)nrow * DM)
                                      : (Wrel + (size_t)(nrow - 3072) * DM);

    const int tx = tid & 15, ty = tid >> 4;
    float acc[8][8];
    #pragma unroll
    for (int i = 0; i < 8; i++)
        #pragma unroll
        for (int j = 0; j < 8; j++) acc[i][j] = 0.f;

    for (int k0 = 0; k0 < DM; k0 += 8) {
        float4 a = *(const float4*)(arow + k0 + kq);
        float4 b = *(const float4*)(brow + k0 + kq);
        As[kq+0][lr]=a.x; As[kq+1][lr]=a.y; As[kq+2][lr]=a.z; As[kq+3][lr]=a.w;
        Bs[kq+0][lr]=b.x; Bs[kq+1][lr]=b.y; Bs[kq+2][lr]=b.z; Bs[kq+3][lr]=b.w;
        __syncthreads();
        #pragma unroll 4
        for (int kk = 0; kk < 8; kk++){
            float av[8], bv[8];
            *(float4*)&av[0] = *(float4*)&As[kk][ty*8];
            *(float4*)&av[4] = *(float4*)&As[kk][ty*8+4];
            *(float4*)&bv[0] = *(float4*)&Bs[kk][tx*8];
            *(float4*)&bv[4] = *(float4*)&Bs[kk][tx*8+4];
            #pragma unroll
            for (int i = 0; i < 8; i++)
                #pragma unroll
                for (int j = 0; j < 8; j++)
                    acc[i][j] = fmaf(av[i], bv[j], acc[i][j]);
        }
        __syncthreads();
    }

    #pragma unroll
    for (int ii = 0; ii < 8; ii++){
        const int mm = bm + ty*8 + ii;
        const int t = mm >> 2, b = mm & 3;
        #pragma unroll
        for (int jj = 0; jj < 8; jj++){
            const int n = bn + tx*8 + jj;
            const float val = acc[ii][jj];
            if (n < 1024) {
                if (t >= MEMN) {
                    const int i = t - MEMN, h = n >> 6, d = n & 63;
                    const size_t off = (((size_t)(b*NH + h))*SEQ + i)*DH + d;
                    g_qu[off] = val + pbu[n];
                    g_qv[off] = val + pbv[n];
                }
            } else if (n < 2048) {
                const int nn = n - 1024, h = nn >> 6, d = nn & 63;
                g_k[(((size_t)(b*NH + h))*TT + t)*DH + d] = val;
            } else if (n < 3072) {
                const int nn = n - 2048, h = nn >> 6, d = nn & 63;
                g_v[(((size_t)(b*NH + h))*TT + t)*DH + d] = val;
            } else {
                const int nn = n - 3072, h = nn >> 6, d = nn & 63;
                g_r[(((size_t)(b*NH + h))*TT + t)*DH + d] = val;
            }
        }
    }
}

// ---------------- kernel 2: AC and BD-raw score GEMMs (K=64) ----------------
// z = bh*2 + which; which==0: AC = qu @ k^T ; which==1: BDraw = qv @ r^T
__global__ __launch_bounds__(256) void score_gemm_kernel()
{
    __shared__ float AsT[64][64];
    __shared__ float BsT[64][64];
    const int z = blockIdx.z;
    const int bh = z >> 1;
    const int which = z & 1;
    const float* Ab = (which ? g_qv : g_qu) + (size_t)bh * SEQ * DH;
    const float* Bb = (which ? g_r  : g_k ) + (size_t)bh * TT  * DH;
    float* Ob = (which ? g_bd : g_ac) + (size_t)bh * SEQ * TT;
    const int i0 = blockIdx.y * 64;
    const int j0 = blockIdx.x * 64;
    const int t = threadIdx.x;
    const int r = t >> 2, cg = t & 3;

    #pragma unroll
    for (int q = 0; q < 4; q++){
        const int col = cg*16 + q*4;
        float4 a = *(const float4*)(Ab + (size_t)(i0+r)*DH + col);
        AsT[col+0][r]=a.x; AsT[col+1][r]=a.y; AsT[col+2][r]=a.z; AsT[col+3][r]=a.w;
        float4 b = *(const float4*)(Bb + (size_t)(j0+r)*DH + col);
        BsT[col+0][r]=b.x; BsT[col+1][r]=b.y; BsT[col+2][r]=b.z; BsT[col+3][r]=b.w;
    }
    __syncthreads();
    const int tx = t & 15, ty = t >> 4;
    float acc[4][4];
    #pragma unroll
    for (int i = 0; i < 4; i++)
        #pragma unroll
        for (int j = 0; j < 4; j++) acc[i][j] = 0.f;

    #pragma unroll 16
    for (int kk = 0; kk < 64; kk++){
        float av[4], bv[4];
        *(float4*)av = *(float4*)&AsT[kk][ty*4];
        *(float4*)bv = *(float4*)&BsT[kk][tx*4];
        #pragma unroll
        for (int i = 0; i < 4; i++)
            #pragma unroll
            for (int j = 0; j < 4; j++)
                acc[i][j] = fmaf(av[i], bv[j], acc[i][j]);
    }
    #pragma unroll
    for (int ii = 0; ii < 4; ii++){
        float4 o = make_float4(acc[ii][0], acc[ii][1], acc[ii][2], acc[ii][3]);
        *(float4*)(Ob + (size_t)(i0 + ty*4 + ii)*TT + j0 + tx*4) = o;
    }
}

// ---------------- kernel 3: rel-shift gather + scale + softmax (exp stage) ----------------
// scores[i,j] = (AC[i,j] + BDshift) * 0.125; write exp(s - rowmax) in place; store 1/rowsum
// BDshift: delta=j-i;  delta<=1024 -> bd[i][delta+1023]; delta==1025 -> 0; else bd[i+1][delta-1026]
__global__ __launch_bounds__(256) void softmax_shift_kernel()
{
    const int i  = blockIdx.x;
    const int bh = blockIdx.y;
    const int t  = threadIdx.x;
    const size_t rowoff = ((size_t)bh*SEQ + i) * TT;
    float* ac = g_ac + rowoff;
    const float* bd0 = g_bd + rowoff;
    const float* bd1 = bd0 + TT;  // row i+1 (only dereferenced when valid)

    float sv[8];
    float lmax = -INFINITY;
    #pragma unroll
    for (int q = 0; q < 8; q++){
        const int j = q*256 + t;
        const int delta = j - i;
        float bd;
        if (delta <= 1024)      bd = bd0[delta + 1023];
        else if (delta == 1025) bd = 0.f;
        else                    bd = bd1[delta - 1026];
        const float s = (ac[j] + bd) * 0.125f;
        sv[q] = s;
        lmax = fmaxf(lmax, s);
    }
    __shared__ float sh[8];
    float wmax = warpReduceMax(lmax);
    if ((t & 31) == 0) sh[t >> 5] = wmax;
    __syncthreads();
    float mx = sh[0];
    #pragma unroll
    for (int w = 1; w < 8; w++) mx = fmaxf(mx, sh[w]);
    __syncthreads();

    float lsum = 0.f;
    #pragma unroll
    for (int q = 0; q < 8; q++){
        const int j = q*256 + t;
        const float p = __expf(sv[q] - mx);
        ac[j] = p;
        lsum += p;
    }
    float wsum = warpReduceSum(lsum);
    if ((t & 31) == 0) sh[t >> 5] = wsum;
    __syncthreads();
    if (t == 0){
        float sum = 0.f;
        #pragma unroll
        for (int w = 0; w < 8; w++) sum += sh[w];
        g_sinv[(size_t)bh*SEQ + i] = 1.f / sum;
    }
}

// ---------------- kernel 4: PV GEMM (M=1024,N=64,K=2048 per head) ----------------
__global__ __launch_bounds__(256) void pv_kernel()
{
    __shared__ float PsT[16][64];
    __shared__ float Vs [16][64];
    const int bh = blockIdx.y;
    const int i0 = blockIdx.x * 64;
    const float* P = g_ac + (size_t)bh*SEQ*TT + (size_t)i0*TT;
    const float* V = g_v + (size_t)bh*TT*DH;
    const int t = threadIdx.x;
    const int r = t >> 2, cg = t & 3;
    const int vr = t >> 4, vc = (t & 15) * 4;
    const int tx = t & 15, ty = t >> 4;

    float acc[4][4];
    #pragma unroll
    for (int i = 0; i < 4; i++)
        #pragma unroll
        for (int j = 0; j < 4; j++) acc[i][j] = 0.f;

    for (int k0 = 0; k0 < TT; k0 += 16) {
        float4 p = *(const float4*)(P + (size_t)r*TT + k0 + cg*4);
        PsT[cg*4+0][r]=p.x; PsT[cg*4+1][r]=p.y; PsT[cg*4+2][r]=p.z; PsT[cg*4+3][r]=p.w;
        *(float4*)&Vs[vr][vc] = *(const float4*)(V + (size_t)(k0 + vr)*DH + vc);
        __syncthreads();
        #pragma unroll
        for (int kk = 0; kk < 16; kk++){
            float av[4], bv[4];
            *(float4*)av = *(float4*)&PsT[kk][ty*4];
            *(float4*)bv = *(float4*)&Vs[kk][tx*4];
            #pragma unroll
            for (int i = 0; i < 4; i++)
                #pragma unroll
                for (int j = 0; j < 4; j++)
                    acc[i][j] = fmaf(av[i], bv[j], acc[i][j]);
        }
        __syncthreads();
    }
    const int b = bh >> 4, h = bh & 15;
    #pragma unroll
    for (int ii = 0; ii < 4; ii++){
        const int i = i0 + ty*4 + ii;
        const float sinv = g_sinv[(size_t)bh*SEQ + i];
        float4 o = make_float4(acc[ii][0]*sinv, acc[ii][1]*sinv,
                               acc[ii][2]*sinv, acc[ii][3]*sinv);
        *(float4*)(g_av + ((size_t)i*BATCH + b)*DM + h*DH + tx*4) = o;
    }
}

// ---------------- kernel 5: out projection + residual ----------------
__global__ __launch_bounds__(256) void outproj_kernel(const float* __restrict__ x,
                                                      const float* __restrict__ Wo,
                                                      float* __restrict__ out)
{
    __shared__ float AsT[16][64];
    __shared__ float BsT[16][64];
    const int m0 = blockIdx.y * 64;
    const int n0 = blockIdx.x * 64;
    const int t = threadIdx.x;
    const int r = t >> 2, cg = t & 3;
    const int tx = t & 15, ty = t >> 4;

    float acc[4][4];
    #pragma unroll
    for (int i = 0; i < 4; i++)
        #pragma unroll
        for (int j = 0; j < 4; j++) acc[i][j] = 0.f;

    for (int k0 = 0; k0 < DM; k0 += 16){
        float4 a = *(const float4*)(g_av + (size_t)(m0+r)*DM + k0 + cg*4);
        AsT[cg*4+0][r]=a.x; AsT[cg*4+1][r]=a.y; AsT[cg*4+2][r]=a.z; AsT[cg*4+3][r]=a.w;
        float4 b = *(const float4*)(Wo + (size_t)(n0+r)*DM + k0 + cg*4);
        BsT[cg*4+0][r]=b.x; BsT[cg*4+1][r]=b.y; BsT[cg*4+2][r]=b.z; BsT[cg*4+3][r]=b.w;
        __syncthreads();
        #pragma unroll
        for (int kk = 0; kk < 16; kk++){
            float av[4], bv[4];
            *(float4*)av = *(float4*)&AsT[kk][ty*4];
            *(float4*)bv = *(float4*)&BsT[kk][tx*4];
            #pragma unroll
            for (int i = 0; i < 4; i++)
                #pragma unroll
                for (int j = 0; j < 4; j++)
                    acc[i][j] = fmaf(av[i], bv[j], acc[i][j]);
        }
        __syncthreads();
    }
    #pragma unroll
    for (int ii = 0; ii < 4; ii++){
        const int m = m0 + ty*4 + ii;
        float4 xr = *(const float4*)(x + (size_t)m*DM + n0 + tx*4);
        float4 o = make_float4(acc[ii][0]+xr.x, acc[ii][1]+xr.y,
                               acc[ii][2]+xr.z, acc[ii][3]+xr.w);
        *(float4*)(out + (size_t)m*DM + n0 + tx*4) = o;
    }
}

// ---------------- kernel 6: LayerNorm (in place on out) ----------------
__global__ __launch_bounds__(256) void ln_kernel(float* __restrict__ out,
                                                 const float* __restrict__ gamma,
                                                 const float* __restrict__ beta)
{
    const int row = blockIdx.x;
    float* y = out + (size_t)row * DM;
    const int t = threadIdx.x;
    float v[4];
    float s = 0.f, sq = 0.f;
    #pragma unroll
    for (int q = 0; q < 4; q++){
        v[q] = y[q*256 + t];
        s += v[q];
        sq += v[q]*v[q];
    }
    __shared__ float sh[16];
    float ws = warpReduceSum(s);
    float wq = warpReduceSum(sq);
    if ((t & 31) == 0){ sh[t>>5] = ws; sh[8 + (t>>5)] = wq; }
    __syncthreads();
    s = 0.f; sq = 0.f;
    #pragma unroll
    for (int w = 0; w < 8; w++){ s += sh[w]; sq += sh[8+w]; }
    const float mu = s * (1.f/1024.f);
    const float var = sq * (1.f/1024.f) - mu*mu;
    const float rstd = rsqrtf(var + 1e-5f);
    #pragma unroll
    for (int q = 0; q < 4; q++){
        const int d = q*256 + t;
        y[d] = gamma[d] * ((v[q] - mu) * rstd) + beta[d];
    }
}

// ---------------- launch ----------------
extern "C" void kernel_launch(void* const* d_in, const int* in_sizes, int n_in,
                              void* d_out, int out_size)
{
    const float* x     = (const float*)d_in[0];
    const float* mem   = (const float*)d_in[1];
    const float* pos   = (const float*)d_in[2];
    const float* pbu   = (const float*)d_in[3];
    const float* pbv   = (const float*)d_in[4];
    const float* Wqkv  = (const float*)d_in[5];
    const float* Wrel  = (const float*)d_in[6];
    const float* Wo    = (const float*)d_in[7];
    const float* gamma = (const float*)d_in[8];
    const float* beta  = (const float*)d_in[9];
    float* out = (float*)d_out;

    proj_kernel<<<dim3(32, 64), 256>>>(x, mem, pos, Wqkv, Wrel, pbu, pbv);
    score_gemm_kernel<<<dim3(32, 16, 128), 256>>>();
    softmax_shift_kernel<<<dim3(1024, 64), 256>>>();
    pv_kernel<<<dim3(16, 64), 256>>>();
    outproj_kernel<<<dim3(16, 64), 256>>>(x, Wo, out);
    ln_kernel<<<4096, 256>>>(out, gamma, beta);
}

// round 2
// speedup vs baseline: 1.6281x; 1.6281x over previous
#include <cuda_runtime.h>
#include <math.h>

#define SEQ   1024
#define MEMN  1024
#define TT    2048
#define BATCH 4
#define NH    16
#define DH    64
#define DM    1024
#define BH    (BATCH*NH)   // 64

// ---------------- scratch (device globals; no allocation allowed) ----------------
__device__ float g_qu[(size_t)BH*SEQ*DH];     // [b][h][i][d]  q + pos_bias_u
__device__ float g_qv[(size_t)BH*SEQ*DH];     // [b][h][i][d]  q + pos_bias_v
__device__ float g_k [(size_t)BH*TT*DH];      // [b][h][t][d]
__device__ float g_v [(size_t)BH*TT*DH];      // [b][h][t][d]
__device__ float g_r [(size_t)BH*TT*DH];      // [b][h][t][d]
__device__ float g_ac[(size_t)BH*SEQ*TT];     // [b][h][i][j]  AC scores -> exp'd probs (in place)
__device__ float g_bd[(size_t)BH*SEQ*TT];     // [b][h][i][e]  BD raw (pre-shift)
__device__ float g_sinv[(size_t)BH*SEQ];      // 1/sum per row
__device__ float g_av[(size_t)SEQ*BATCH*DM];  // attn_vec, rows = (i*B+b), cols = h*64+d

// ---------------- reductions ----------------
__device__ __forceinline__ float warpReduceSum(float v){
    #pragma unroll
    for (int o = 16; o > 0; o >>= 1) v += __shfl_xor_sync(0xffffffffu, v, o);
    return v;
}
__device__ __forceinline__ float warpReduceMax(float v){
    #pragma unroll
    for (int o = 16; o > 0; o >>= 1) v = fmaxf(v, __shfl_xor_sync(0xffffffffu, v, o));
    return v;
}

// ---------------- kernel 1: fused QKV + R projection GEMM ----------------
// out[m,n] = sum_k A[m,k] * W[n,k]
//   n in [0,3072):  A = concat(memory, x) row m, W = W_qkv
//   n in [3072,4096): A = pos_emb row m,     W = W_rel
__global__ __launch_bounds__(256) void proj_kernel(
    const float* __restrict__ x, const float* __restrict__ mem,
    const float* __restrict__ pos, const float* __restrict__ Wqkv,
    const float* __restrict__ Wrel, const float* __restrict__ pbu,
    const float* __restrict__ pbv)
{
    __shared__ float As[16][128];
    __shared__ float Bs[16][128];
    const int bm = blockIdx.y * 128;
    const int bn = blockIdx.x * 128;
    const int tid = threadIdx.x;
    const int lr = tid >> 1;          // 0..127
    const int kh = (tid & 1) * 8;     // 0 or 8

    const int m = bm + lr;
    const float* arow;
    if (bn >= 3072) arow = pos + (size_t)m * DM;
    else arow = (m < MEMN*BATCH) ? (mem + (size_t)m * DM)
                                 : (x + (size_t)(m - MEMN*BATCH) * DM);
    const int nrow = bn + lr;
    const float* brow = (nrow < 3072) ? (Wqkv + (size_t)nrow * DM)
                                      : (Wrel + (size_t)(nrow - 3072) * DM);

    const int tx = tid & 15, ty = tid >> 4;
    float acc[8][8];
    #pragma unroll
    for (int i = 0; i < 8; i++)
        #pragma unroll
        for (int j = 0; j < 8; j++) acc[i][j] = 0.f;

    for (int k0 = 0; k0 < DM; k0 += 16) {
        #pragma unroll
        for (int q = 0; q < 2; q++){
            const int c = kh + q*4;
            float4 a = *(const float4*)(arow + k0 + c);
            float4 b = *(const float4*)(brow + k0 + c);
            As[c+0][lr]=a.x; As[c+1][lr]=a.y; As[c+2][lr]=a.z; As[c+3][lr]=a.w;
            Bs[c+0][lr]=b.x; Bs[c+1][lr]=b.y; Bs[c+2][lr]=b.z; Bs[c+3][lr]=b.w;
        }
        __syncthreads();
        #pragma unroll 8
        for (int kk = 0; kk < 16; kk++){
            float av[8], bv[8];
            *(float4*)&av[0] = *(float4*)&As[kk][ty*8];
            *(float4*)&av[4] = *(float4*)&As[kk][ty*8+4];
            *(float4*)&bv[0] = *(float4*)&Bs[kk][tx*8];
            *(float4*)&bv[4] = *(float4*)&Bs[kk][tx*8+4];
            #pragma unroll
            for (int i = 0; i < 8; i++)
                #pragma unroll
                for (int j = 0; j < 8; j++)
                    acc[i][j] = fmaf(av[i], bv[j], acc[i][j]);
        }
        __syncthreads();
    }

    #pragma unroll
    for (int ii = 0; ii < 8; ii++){
        const int mm = bm + ty*8 + ii;
        const int t = mm >> 2, b = mm & 3;
        #pragma unroll
        for (int jj = 0; jj < 8; jj++){
            const int n = bn + tx*8 + jj;
            const float val = acc[ii][jj];
            if (n < 1024) {
                if (t >= MEMN) {
                    const int i = t - MEMN, h = n >> 6, d = n & 63;
                    const size_t off = (((size_t)(b*NH + h))*SEQ + i)*DH + d;
                    g_qu[off] = val + pbu[n];
                    g_qv[off] = val + pbv[n];
                }
            } else if (n < 2048) {
                const int nn = n - 1024, h = nn >> 6, d = nn & 63;
                g_k[(((size_t)(b*NH + h))*TT + t)*DH + d] = val;
            } else if (n < 3072) {
                const int nn = n - 2048, h = nn >> 6, d = nn & 63;
                g_v[(((size_t)(b*NH + h))*TT + t)*DH + d] = val;
            } else {
                const int nn = n - 3072, h = nn >> 6, d = nn & 63;
                g_r[(((size_t)(b*NH + h))*TT + t)*DH + d] = val;
            }
        }
    }
}

// ---------------- kernel 2: AC and BD-raw score GEMMs (K=64) ----------------
// 128x128 tiles, 8x8 per thread, K-step 32 (two passes over K=64)
// z = bh*2 + which; which==0: AC = qu @ k^T ; which==1: BDraw = qv @ r^T
__global__ __launch_bounds__(256) void score_gemm_kernel()
{
    __shared__ float AsT[32][128];
    __shared__ float BsT[32][128];
    const int z = blockIdx.z;
    const int bh = z >> 1;
    const int which = z & 1;
    const float* Ab = (which ? g_qv : g_qu) + (size_t)bh * SEQ * DH;
    const float* Bb = (which ? g_r  : g_k ) + (size_t)bh * TT  * DH;
    float* Ob = (which ? g_bd : g_ac) + (size_t)bh * SEQ * TT;
    const int i0 = blockIdx.y * 128;
    const int j0 = blockIdx.x * 128;
    const int t = threadIdx.x;
    const int lr = t >> 1;          // 0..127
    const int kh = (t & 1) * 16;    // 0 or 16
    const int tx = t & 15, ty = t >> 4;

    float acc[8][8];
    #pragma unroll
    for (int i = 0; i < 8; i++)
        #pragma unroll
        for (int j = 0; j < 8; j++) acc[i][j] = 0.f;

    #pragma unroll
    for (int ks = 0; ks < 64; ks += 32) {
        #pragma unroll
        for (int q = 0; q < 4; q++){
            const int c = kh + q*4;
            float4 a = *(const float4*)(Ab + (size_t)(i0+lr)*DH + ks + c);
            AsT[c+0][lr]=a.x; AsT[c+1][lr]=a.y; AsT[c+2][lr]=a.z; AsT[c+3][lr]=a.w;
            float4 b = *(const float4*)(Bb + (size_t)(j0+lr)*DH + ks + c);
            BsT[c+0][lr]=b.x; BsT[c+1][lr]=b.y; BsT[c+2][lr]=b.z; BsT[c+3][lr]=b.w;
        }
        __syncthreads();
        #pragma unroll 8
        for (int kk = 0; kk < 32; kk++){
            float av[8], bv[8];
            *(float4*)&av[0] = *(float4*)&AsT[kk][ty*8];
            *(float4*)&av[4] = *(float4*)&AsT[kk][ty*8+4];
            *(float4*)&bv[0] = *(float4*)&BsT[kk][tx*8];
            *(float4*)&bv[4] = *(float4*)&BsT[kk][tx*8+4];
            #pragma unroll
            for (int i = 0; i < 8; i++)
                #pragma unroll
                for (int j = 0; j < 8; j++)
                    acc[i][j] = fmaf(av[i], bv[j], acc[i][j]);
        }
        __syncthreads();
    }
    #pragma unroll
    for (int ii = 0; ii < 8; ii++){
        float* orow = Ob + (size_t)(i0 + ty*8 + ii)*TT + j0 + tx*8;
        *(float4*)(orow)     = make_float4(acc[ii][0], acc[ii][1], acc[ii][2], acc[ii][3]);
        *(float4*)(orow + 4) = make_float4(acc[ii][4], acc[ii][5], acc[ii][6], acc[ii][7]);
    }
}

// ---------------- kernel 3: rel-shift gather + scale + softmax (exp stage) ----------------
__global__ __launch_bounds__(256) void softmax_shift_kernel()
{
    const int i  = blockIdx.x;
    const int bh = blockIdx.y;
    const int t  = threadIdx.x;
    const size_t rowoff = ((size_t)bh*SEQ + i) * TT;
    float* ac = g_ac + rowoff;
    const float* bd0 = g_bd + rowoff;
    const float* bd1 = bd0 + TT;  // row i+1 (only dereferenced when valid)

    float sv[8];
    float lmax = -INFINITY;
    #pragma unroll
    for (int q = 0; q < 8; q++){
        const int j = q*256 + t;
        const int delta = j - i;
        float bd;
        if (delta <= 1024)      bd = bd0[delta + 1023];
        else if (delta == 1025) bd = 0.f;
        else                    bd = bd1[delta - 1026];
        const float s = (ac[j] + bd) * 0.125f;
        sv[q] = s;
        lmax = fmaxf(lmax, s);
    }
    __shared__ float sh[8];
    float wmax = warpReduceMax(lmax);
    if ((t & 31) == 0) sh[t >> 5] = wmax;
    __syncthreads();
    float mx = sh[0];
    #pragma unroll
    for (int w = 1; w < 8; w++) mx = fmaxf(mx, sh[w]);
    __syncthreads();

    float lsum = 0.f;
    #pragma unroll
    for (int q = 0; q < 8; q++){
        const int j = q*256 + t;
        const float p = __expf(sv[q] - mx);
        ac[j] = p;
        lsum += p;
    }
    float wsum = warpReduceSum(lsum);
    if ((t & 31) == 0) sh[t >> 5] = wsum;
    __syncthreads();
    if (t == 0){
        float sum = 0.f;
        #pragma unroll
        for (int w = 0; w < 8; w++) sum += sh[w];
        g_sinv[(size_t)bh*SEQ + i] = 1.f / sum;
    }
}

// ---------------- kernel 4: PV GEMM (M=1024,N=64,K=2048 per head) ----------------
// 128x64 tiles, 256 threads, 4x8 per thread, K-step 32
__global__ __launch_bounds__(256) void pv_kernel()
{
    __shared__ float PsT[32][128];
    __shared__ float Vs [32][64];
    const int bh = blockIdx.y;
    const int i0 = blockIdx.x * 128;
    const float* P = g_ac + (size_t)bh*SEQ*TT + (size_t)i0*TT;
    const float* V = g_v + (size_t)bh*TT*DH;
    const int t = threadIdx.x;
    const int lr = t >> 1;          // 0..127 (P loader row)
    const int kh = (t & 1) * 16;    // 0 or 16
    const int vr = t >> 3;          // 0..31  (V loader row)
    const int vc = (t & 7) * 8;     // 0..56
    const int tx = t & 7;           // 0..7  -> cols tx*8
    const int ty = t >> 3;          // 0..31 -> rows ty*4

    float acc[4][8];
    #pragma unroll
    for (int i = 0; i < 4; i++)
        #pragma unroll
        for (int j = 0; j < 8; j++) acc[i][j] = 0.f;

    for (int k0 = 0; k0 < TT; k0 += 32) {
        #pragma unroll
        for (int q = 0; q < 4; q++){
            const int c = kh + q*4;
            float4 p = *(const float4*)(P + (size_t)lr*TT + k0 + c);
            PsT[c+0][lr]=p.x; PsT[c+1][lr]=p.y; PsT[c+2][lr]=p.z; PsT[c+3][lr]=p.w;
        }
        *(float4*)&Vs[vr][vc]   = *(const float4*)(V + (size_t)(k0 + vr)*DH + vc);
        *(float4*)&Vs[vr][vc+4] = *(const float4*)(V + (size_t)(k0 + vr)*DH + vc + 4);
        __syncthreads();
        #pragma unroll 8
        for (int kk = 0; kk < 32; kk++){
            float av[4], bv[8];
            *(float4*)av = *(float4*)&PsT[kk][ty*4];
            *(float4*)&bv[0] = *(float4*)&Vs[kk][tx*8];
            *(float4*)&bv[4] = *(float4*)&Vs[kk][tx*8+4];
            #pragma unroll
            for (int i = 0; i < 4; i++)
                #pragma unroll
                for (int j = 0; j < 8; j++)
                    acc[i][j] = fmaf(av[i], bv[j], acc[i][j]);
        }
        __syncthreads();
    }
    const int b = bh >> 4, h = bh & 15;
    #pragma unroll
    for (int ii = 0; ii < 4; ii++){
        const int i = i0 + ty*4 + ii;
        const float sinv = g_sinv[(size_t)bh*SEQ + i];
        float* orow = g_av + ((size_t)i*BATCH + b)*DM + h*DH + tx*8;
        *(float4*)(orow)     = make_float4(acc[ii][0]*sinv, acc[ii][1]*sinv,
                                           acc[ii][2]*sinv, acc[ii][3]*sinv);
        *(float4*)(orow + 4) = make_float4(acc[ii][4]*sinv, acc[ii][5]*sinv,
                                           acc[ii][6]*sinv, acc[ii][7]*sinv);
    }
}

// ---------------- kernel 5: out projection + residual ----------------
// 128x128 tiles, 8x8 per thread, K-step 16
__global__ __launch_bounds__(256) void outproj_kernel(const float* __restrict__ x,
                                                      const float* __restrict__ Wo,
                                                      float* __restrict__ out)
{
    __shared__ float As[16][128];
    __shared__ float Bs[16][128];
    const int m0 = blockIdx.y * 128;
    const int n0 = blockIdx.x * 128;
    const int t = threadIdx.x;
    const int lr = t >> 1;
    const int kh = (t & 1) * 8;
    const int tx = t & 15, ty = t >> 4;

    float acc[8][8];
    #pragma unroll
    for (int i = 0; i < 8; i++)
        #pragma unroll
        for (int j = 0; j < 8; j++) acc[i][j] = 0.f;

    for (int k0 = 0; k0 < DM; k0 += 16){
        #pragma unroll
        for (int q = 0; q < 2; q++){
            const int c = kh + q*4;
            float4 a = *(const float4*)(g_av + (size_t)(m0+lr)*DM + k0 + c);
            As[c+0][lr]=a.x; As[c+1][lr]=a.y; As[c+2][lr]=a.z; As[c+3][lr]=a.w;
            float4 b = *(const float4*)(Wo + (size_t)(n0+lr)*DM + k0 + c);
            Bs[c+0][lr]=b.x; Bs[c+1][lr]=b.y; Bs[c+2][lr]=b.z; Bs[c+3][lr]=b.w;
        }
        __syncthreads();
        #pragma unroll 8
        for (int kk = 0; kk < 16; kk++){
            float av[8], bv[8];
            *(float4*)&av[0] = *(float4*)&As[kk][ty*8];
            *(float4*)&av[4] = *(float4*)&As[kk][ty*8+4];
            *(float4*)&bv[0] = *(float4*)&Bs[kk][tx*8];
            *(float4*)&bv[4] = *(float4*)&Bs[kk][tx*8+4];
            #pragma unroll
            for (int i = 0; i < 8; i++)
                #pragma unroll
                for (int j = 0; j < 8; j++)
                    acc[i][j] = fmaf(av[i], bv[j], acc[i][j]);
        }
        __syncthreads();
    }
    #pragma unroll
    for (int ii = 0; ii < 8; ii++){
        const int m = m0 + ty*8 + ii;
        #pragma unroll
        for (int jh = 0; jh < 2; jh++){
            float4 xr = *(const float4*)(x + (size_t)m*DM + n0 + tx*8 + jh*4);
            float4 o = make_float4(acc[ii][jh*4+0]+xr.x, acc[ii][jh*4+1]+xr.y,
                                   acc[ii][jh*4+2]+xr.z, acc[ii][jh*4+3]+xr.w);
            *(float4*)(out + (size_t)m*DM + n0 + tx*8 + jh*4) = o;
        }
    }
}

// ---------------- kernel 6: LayerNorm (in place on out) ----------------
__global__ __launch_bounds__(256) void ln_kernel(float* __restrict__ out,
                                                 const float* __restrict__ gamma,
                                                 const float* __restrict__ beta)
{
    const int row = blockIdx.x;
    float* y = out + (size_t)row * DM;
    const int t = threadIdx.x;
    float v[4];
    float s = 0.f, sq = 0.f;
    #pragma unroll
    for (int q = 0; q < 4; q++){
        v[q] = y[q*256 + t];
        s += v[q];
        sq += v[q]*v[q];
    }
    __shared__ float sh[16];
    float ws = warpReduceSum(s);
    float wq = warpReduceSum(sq);
    if ((t & 31) == 0){ sh[t>>5] = ws; sh[8 + (t>>5)] = wq; }
    __syncthreads();
    s = 0.f; sq = 0.f;
    #pragma unroll
    for (int w = 0; w < 8; w++){ s += sh[w]; sq += sh[8+w]; }
    const float mu = s * (1.f/1024.f);
    const float var = sq * (1.f/1024.f) - mu*mu;
    const float rstd = rsqrtf(var + 1e-5f);
    #pragma unroll
    for (int q = 0; q < 4; q++){
        const int d = q*256 + t;
        y[d] = gamma[d] * ((v[q] - mu) * rstd) + beta[d];
    }
}

// ---------------- launch ----------------
extern "C" void kernel_launch(void* const* d_in, const int* in_sizes, int n_in,
                              void* d_out, int out_size)
{
    const float* x     = (const float*)d_in[0];
    const float* mem   = (const float*)d_in[1];
    const float* pos   = (const float*)d_in[2];
    const float* pbu   = (const float*)d_in[3];
    const float* pbv   = (const float*)d_in[4];
    const float* Wqkv  = (const float*)d_in[5];
    const float* Wrel  = (const float*)d_in[6];
    const float* Wo    = (const float*)d_in[7];
    const float* gamma = (const float*)d_in[8];
    const float* beta  = (const float*)d_in[9];
    float* out = (float*)d_out;

    proj_kernel<<<dim3(32, 64), 256>>>(x, mem, pos, Wqkv, Wrel, pbu, pbv);
    score_gemm_kernel<<<dim3(16, 8, 128), 256>>>();
    softmax_shift_kernel<<<dim3(1024, 64), 256>>>();
    pv_kernel<<<dim3(8, 64), 256>>>();
    outproj_kernel<<<dim3(8, 32), 256>>>(x, Wo, out);
    ln_kernel<<<4096, 256>>>(out, gamma, beta);
}

// round 4
// speedup vs baseline: 2.1876x; 1.3436x over previous
#include <cuda_runtime.h>
#include <cuda_bf16.h>
#include <math.h>
#include <stdint.h>

#define SEQ   1024
#define MEMN  1024
#define TT    2048
#define BATCH 4
#define NH    16
#define DH    64
#define DM    1024
#define BH    (BATCH*NH)   // 64

// ---------------- scratch (device globals; no allocation allowed) ----------------
__device__ float g_qu[(size_t)BH*SEQ*DH];
__device__ float g_qv[(size_t)BH*SEQ*DH];
__device__ float g_k [(size_t)BH*TT*DH];
__device__ float g_v [(size_t)BH*TT*DH];
__device__ float g_r [(size_t)BH*TT*DH];
__device__ float g_ac[(size_t)BH*SEQ*TT];
__device__ float g_bd[(size_t)BH*SEQ*TT];
__device__ float g_sinv[(size_t)BH*SEQ];
__device__ float g_av[(size_t)SEQ*BATCH*DM];

// bf16 hi/lo split operands for tensor-core projection
__device__ __nv_bfloat16 g_chi[(size_t)8192*1024];
__device__ __nv_bfloat16 g_clo[(size_t)8192*1024];
__device__ __nv_bfloat16 g_phi[(size_t)8192*1024];
__device__ __nv_bfloat16 g_plo[(size_t)8192*1024];
__device__ __nv_bfloat16 g_whi[(size_t)4096*1024];
__device__ __nv_bfloat16 g_wlo[(size_t)4096*1024];

// ---------------- helpers ----------------
__device__ __forceinline__ uint32_t smem_u32(const void* p){
    uint32_t a;
    asm("{ .reg .u64 t; cvta.to.shared.u64 t, %1; cvt.u32.u64 %0, t; }" : "=r"(a) : "l"(p));
    return a;
}
__device__ __forceinline__ void cp16(uint32_t s, const void* g){
    asm volatile("cp.async.cg.shared.global [%0], [%1], 16;" :: "r"(s), "l"(g));
}
#define CP_COMMIT() asm volatile("cp.async.commit_group;" ::: "memory")
#define CP_WAIT0()  asm volatile("cp.async.wait_group 0;" ::: "memory")

__device__ __forceinline__ void ldm4(uint32_t* r, uint32_t addr){
    asm volatile("ldmatrix.sync.aligned.m8n8.x4.shared.b16 {%0,%1,%2,%3}, [%4];"
        : "=r"(r[0]), "=r"(r[1]), "=r"(r[2]), "=r"(r[3]) : "r"(addr));
}
__device__ __forceinline__ void mma_bf16(float* c, const uint32_t* a, uint32_t b0, uint32_t b1){
    asm volatile("mma.sync.aligned.m16n8k16.row.col.f32.bf16.bf16.f32 "
        "{%0,%1,%2,%3}, {%4,%5,%6,%7}, {%8,%9}, {%0,%1,%2,%3};"
        : "+f"(c[0]), "+f"(c[1]), "+f"(c[2]), "+f"(c[3])
        : "r"(a[0]), "r"(a[1]), "r"(a[2]), "r"(a[3]), "r"(b0), "r"(b1));
}

// ---------------- reductions ----------------
__device__ __forceinline__ float warpReduceSum(float v){
    #pragma unroll
    for (int o = 16; o > 0; o >>= 1) v += __shfl_xor_sync(0xffffffffu, v, o);
    return v;
}
__device__ __forceinline__ float warpReduceMax(float v){
    #pragma unroll
    for (int o = 16; o > 0; o >>= 1) v = fmaxf(v, __shfl_xor_sync(0xffffffffu, v, o));
    return v;
}

// ---------------- kernel 0: fp32 -> bf16 hi/lo conversion prepass ----------------
__global__ __launch_bounds__(256) void conv_kernel(
    const float* __restrict__ x, const float* __restrict__ mem,
    const float* __restrict__ pos, const float* __restrict__ Wqkv,
    const float* __restrict__ Wrel)
{
    const size_t u = (size_t)blockIdx.x * 256 + threadIdx.x;   // float4 index, < 5242880
    const float* src;
    __nv_bfloat16 *dhi, *dlo;
    size_t elem;
    if (u < 2097152) {                      // c = concat(mem, x) rows (t*4+b)
        elem = u * 4;
        const size_t row = elem >> 10, col = elem & 1023;
        src = (row < 4096) ? (mem + row*1024 + col) : (x + (row-4096)*1024 + col);
        dhi = g_chi + elem; dlo = g_clo + elem;
    } else if (u < 4194304) {               // pos
        elem = (u - 2097152) * 4;
        src = pos + elem;
        dhi = g_phi + elem; dlo = g_plo + elem;
    } else {                                // W = concat(Wqkv, Wrel)
        elem = (u - 4194304) * 4;
        const size_t row = elem >> 10, col = elem & 1023;
        src = (row < 3072) ? (Wqkv + row*1024 + col) : (Wrel + (row-3072)*1024 + col);
        dhi = g_whi + elem; dlo = g_wlo + elem;
    }
    float4 v = *(const float4*)src;
    __nv_bfloat16 h0 = __float2bfloat16(v.x), h1 = __float2bfloat16(v.y);
    __nv_bfloat16 h2 = __float2bfloat16(v.z), h3 = __float2bfloat16(v.w);
    __nv_bfloat16 l0 = __float2bfloat16(v.x - __bfloat162float(h0));
    __nv_bfloat16 l1 = __float2bfloat16(v.y - __bfloat162float(h1));
    __nv_bfloat16 l2 = __float2bfloat16(v.z - __bfloat162float(h2));
    __nv_bfloat16 l3 = __float2bfloat16(v.w - __bfloat162float(h3));
    uint2 ph, pl;
    ph.x = ((uint32_t)__bfloat16_as_ushort(h1) << 16) | __bfloat16_as_ushort(h0);
    ph.y = ((uint32_t)__bfloat16_as_ushort(h3) << 16) | __bfloat16_as_ushort(h2);
    pl.x = ((uint32_t)__bfloat16_as_ushort(l1) << 16) | __bfloat16_as_ushort(l0);
    pl.y = ((uint32_t)__bfloat16_as_ushort(l3) << 16) | __bfloat16_as_ushort(l2);
    *(uint2*)(dhi) = ph;
    *(uint2*)(dlo) = pl;
}

// ---------------- kernel 1: bf16-split projection GEMM via mma.sync ----------------
// C[8192, 4096] = A[8192,1024] @ W[4096,1024]^T, A/W split hi+lo, 3 products.
// CTA tile 128x128, 8 warps (4M x 2N), warp tile 32x64, K-chunks of 32, cp.async x2 buf.
// SMEM per buffer: Ah | Al | Bh | Bl, each 128 rows x 32 bf16, row stride 40 elems (80 B).
#define PJ_BUF   40960
#define PJ_SMEM  (2*PJ_BUF)   // 81920; epilogue staging 128*132*4=67584 reuses it

__global__ __launch_bounds__(256) void proj_mma_kernel(
    const float* __restrict__ pbu, const float* __restrict__ pbv)
{
    extern __shared__ __align__(128) char smem[];
    const uint32_t sbase = smem_u32(smem);
    const int tid = threadIdx.x, lane = tid & 31, wid = tid >> 5;
    const int n0 = blockIdx.x * 128;
    const int m0 = blockIdx.y * 128;
    const bool is_rel = (n0 >= 3072);
    const __nv_bfloat16* Ahp = (is_rel ? g_phi : g_chi) + (size_t)m0 * 1024;
    const __nv_bfloat16* Alp = (is_rel ? g_plo : g_clo) + (size_t)m0 * 1024;
    const __nv_bfloat16* Bhp = g_whi + (size_t)n0 * 1024;
    const __nv_bfloat16* Blp = g_wlo + (size_t)n0 * 1024;

    const int wm = (wid & 3) * 32;   // warp M offset
    const int wn = (wid >> 2) * 64;  // warp N offset
    const int lsel = (lane < 16) ? lane : (lane - 16);
    const int kof  = (lane < 16) ? 0 : 8;

    float acc[2][8][4];
    #pragma unroll
    for (int mt = 0; mt < 2; mt++)
        #pragma unroll
        for (int nt = 0; nt < 8; nt++)
            #pragma unroll
            for (int q = 0; q < 4; q++) acc[mt][nt][q] = 0.f;

    // chunk loader: 32 K-elems into buffer b
    auto issue = [&](int c, int b){
        const int k0 = c * 32;
        const uint32_t sb = sbase + b * PJ_BUF;
        #pragma unroll
        for (int p = 0; p < 2; p++){
            const int u = p * 256 + tid;
            const int row = u >> 2, seg = u & 3;
            const size_t go = (size_t)row * 1024 + k0 + seg * 8;
            const uint32_t so = row * 80 + seg * 16;
            cp16(sb + so,          Ahp + go);
            cp16(sb + 10240 + so,  Alp + go);
            cp16(sb + 20480 + so,  Bhp + go);
            cp16(sb + 30720 + so,  Blp + go);
        }
        CP_COMMIT();
    };

    issue(0, 0);

    for (int c = 0; c < 32; c++){
        CP_WAIT0();
        __syncthreads();
        if (c + 1 < 32) issue(c + 1, (c + 1) & 1);
        const uint32_t sb = sbase + (c & 1) * PJ_BUF;
        #pragma unroll
        for (int kk = 0; kk < 32; kk += 16){
            uint32_t ah[2][4], al[2][4], bh[4][4], bl[4][4];
            #pragma unroll
            for (int mt = 0; mt < 2; mt++){
                const uint32_t ad = sb + (wm + mt*16 + lsel) * 80 + (kk + kof) * 2;
                ldm4(ah[mt], ad);
                ldm4(al[mt], ad + 10240);
            }
            #pragma unroll
            for (int g = 0; g < 4; g++){
                const uint32_t bd = sb + 20480 + (wn + g*16 + lsel) * 80 + (kk + kof) * 2;
                ldm4(bh[g], bd);
                ldm4(bl[g], bd + 10240);
            }
            #pragma unroll
            for (int mt = 0; mt < 2; mt++)
                #pragma unroll
                for (int nt = 0; nt < 8; nt++){
                    const int g = nt >> 1, s = nt & 1;
                    mma_bf16(acc[mt][nt], ah[mt], bh[g][s], bh[g][s+2]);
                    mma_bf16(acc[mt][nt], ah[mt], bl[g][s], bl[g][s+2]);
                    mma_bf16(acc[mt][nt], al[mt], bh[g][s], bh[g][s+2]);
                }
        }
    }

    // ---- epilogue: stage fp32 tile in SMEM (stride 132), then scatter ----
    __syncthreads();
    float* stg = (float*)smem;
    const int fr = lane >> 2, fc = (lane & 3) * 2;
    #pragma unroll
    for (int mt = 0; mt < 2; mt++)
        #pragma unroll
        for (int nt = 0; nt < 8; nt++){
            const int col = wn + nt*8 + fc;
            const int row0 = wm + mt*16 + fr;
            stg[row0*132 + col]       = acc[mt][nt][0];
            stg[row0*132 + col + 1]   = acc[mt][nt][1];
            stg[(row0+8)*132 + col]   = acc[mt][nt][2];
            stg[(row0+8)*132 + col+1] = acc[mt][nt][3];
        }
    __syncthreads();

    const int rr = tid >> 1, hf = tid & 1;
    const int m = m0 + rr;
    const int t_ = m >> 2, b_ = m & 3;
    const float* src = stg + rr * 132 + hf * 64;
    const int nbase = n0 + hf * 64;
    const int cat = n0 >> 10;             // 0=q 1=k 2=v 3=r (tile fits one category)
    if (cat == 0){
        if (t_ >= MEMN){
            const int i = t_ - MEMN;
            const int h = nbase >> 6;
            const size_t off = (((size_t)(b_*NH + h))*SEQ + i)*DH;
            #pragma unroll
            for (int s = 0; s < 16; s++){
                float4 v  = *(const float4*)(src + s*4);
                float4 pu = *(const float4*)(pbu + nbase + s*4);
                float4 pv = *(const float4*)(pbv + nbase + s*4);
                *(float4*)(g_qu + off + s*4) = make_float4(v.x+pu.x, v.y+pu.y, v.z+pu.z, v.w+pu.w);
                *(float4*)(g_qv + off + s*4) = make_float4(v.x+pv.x, v.y+pv.y, v.z+pv.z, v.w+pv.w);
            }
        }
    } else {
        const int nn = nbase - cat*1024;
        const int h = nn >> 6;
        float* base = (cat == 1) ? g_k : (cat == 2) ? g_v : g_r;
        float* dst = base + (((size_t)(b_*NH + h))*TT + t_)*DH;
        #pragma unroll
        for (int s = 0; s < 16; s++)
            *(float4*)(dst + s*4) = *(const float4*)(src + s*4);
    }
}

// ---------------- kernel 2: AC and BD-raw score GEMMs (K=64, fp32) ----------------
__global__ __launch_bounds__(256) void score_gemm_kernel()
{
    __shared__ float AsT[32][128];
    __shared__ float BsT[32][128];
    const int z = blockIdx.z;
    const int bh = z >> 1;
    const int which = z & 1;
    const float* Ab = (which ? g_qv : g_qu) + (size_t)bh * SEQ * DH;
    const float* Bb = (which ? g_r  : g_k ) + (size_t)bh * TT  * DH;
    float* Ob = (which ? g_bd : g_ac) + (size_t)bh * SEQ * TT;
    const int i0 = blockIdx.y * 128;
    const int j0 = blockIdx.x * 128;
    const int t = threadIdx.x;
    const int lr = t >> 1;
    const int kh = (t & 1) * 16;
    const int tx = t & 15, ty = t >> 4;

    float acc[8][8];
    #pragma unroll
    for (int i = 0; i < 8; i++)
        #pragma unroll
        for (int j = 0; j < 8; j++) acc[i][j] = 0.f;

    #pragma unroll
    for (int ks = 0; ks < 64; ks += 32) {
        #pragma unroll
        for (int q = 0; q < 4; q++){
            const int c = kh + q*4;
            float4 a = *(const float4*)(Ab + (size_t)(i0+lr)*DH + ks + c);
            AsT[c+0][lr]=a.x; AsT[c+1][lr]=a.y; AsT[c+2][lr]=a.z; AsT[c+3][lr]=a.w;
            float4 b = *(const float4*)(Bb + (size_t)(j0+lr)*DH + ks + c);
            BsT[c+0][lr]=b.x; BsT[c+1][lr]=b.y; BsT[c+2][lr]=b.z; BsT[c+3][lr]=b.w;
        }
        __syncthreads();
        #pragma unroll 8
        for (int kk = 0; kk < 32; kk++){
            float av[8], bv[8];
            *(float4*)&av[0] = *(float4*)&AsT[kk][ty*8];
            *(float4*)&av[4] = *(float4*)&AsT[kk][ty*8+4];
            *(float4*)&bv[0] = *(float4*)&BsT[kk][tx*8];
            *(float4*)&bv[4] = *(float4*)&BsT[kk][tx*8+4];
            #pragma unroll
            for (int i = 0; i < 8; i++)
                #pragma unroll
                for (int j = 0; j < 8; j++)
                    acc[i][j] = fmaf(av[i], bv[j], acc[i][j]);
        }
        __syncthreads();
    }
    #pragma unroll
    for (int ii = 0; ii < 8; ii++){
        float* orow = Ob + (size_t)(i0 + ty*8 + ii)*TT + j0 + tx*8;
        *(float4*)(orow)     = make_float4(acc[ii][0], acc[ii][1], acc[ii][2], acc[ii][3]);
        *(float4*)(orow + 4) = make_float4(acc[ii][4], acc[ii][5], acc[ii][6], acc[ii][7]);
    }
}

// ---------------- kernel 3: rel-shift gather + scale + softmax ----------------
__global__ __launch_bounds__(256) void softmax_shift_kernel()
{
    const int i  = blockIdx.x;
    const int bh = blockIdx.y;
    const int t  = threadIdx.x;
    const size_t rowoff = ((size_t)bh*SEQ + i) * TT;
    float* ac = g_ac + rowoff;
    const float* bd0 = g_bd + rowoff;
    const float* bd1 = bd0 + TT;

    float sv[8];
    float lmax = -INFINITY;
    #pragma unroll
    for (int q = 0; q < 8; q++){
        const int j = q*256 + t;
        const int delta = j - i;
        float bd;
        if (delta <= 1024)      bd = bd0[delta + 1023];
        else if (delta == 1025) bd = 0.f;
        else                    bd = bd1[delta - 1026];
        const float s = (ac[j] + bd) * 0.125f;
        sv[q] = s;
        lmax = fmaxf(lmax, s);
    }
    __shared__ float sh[8];
    float wmax = warpReduceMax(lmax);
    if ((t & 31) == 0) sh[t >> 5] = wmax;
    __syncthreads();
    float mx = sh[0];
    #pragma unroll
    for (int w = 1; w < 8; w++) mx = fmaxf(mx, sh[w]);
    __syncthreads();

    float lsum = 0.f;
    #pragma unroll
    for (int q = 0; q < 8; q++){
        const int j = q*256 + t;
        const float p = __expf(sv[q] - mx);
        ac[j] = p;
        lsum += p;
    }
    float wsum = warpReduceSum(lsum);
    if ((t & 31) == 0) sh[t >> 5] = wsum;
    __syncthreads();
    if (t == 0){
        float sum = 0.f;
        #pragma unroll
        for (int w = 0; w < 8; w++) sum += sh[w];
        g_sinv[(size_t)bh*SEQ + i] = 1.f / sum;
    }
}

// ---------------- kernel 4: PV GEMM ----------------
__global__ __launch_bounds__(256) void pv_kernel()
{
    __shared__ float PsT[32][128];
    __shared__ float Vs [32][64];
    const int bh = blockIdx.y;
    const int i0 = blockIdx.x * 128;
    const float* P = g_ac + (size_t)bh*SEQ*TT + (size_t)i0*TT;
    const float* V = g_v + (size_t)bh*TT*DH;
    const int t = threadIdx.x;
    const int lr = t >> 1;
    const int kh = (t & 1) * 16;
    const int vr = t >> 3;
    const int vc = (t & 7) * 8;
    const int tx = t & 7;
    const int ty = t >> 3;

    float acc[4][8];
    #pragma unroll
    for (int i = 0; i < 4; i++)
        #pragma unroll
        for (int j = 0; j < 8; j++) acc[i][j] = 0.f;

    for (int k0 = 0; k0 < TT; k0 += 32) {
        #pragma unroll
        for (int q = 0; q < 4; q++){
            const int c = kh + q*4;
            float4 p = *(const float4*)(P + (size_t)lr*TT + k0 + c);
            PsT[c+0][lr]=p.x; PsT[c+1][lr]=p.y; PsT[c+2][lr]=p.z; PsT[c+3][lr]=p.w;
        }
        *(float4*)&Vs[vr][vc]   = *(const float4*)(V + (size_t)(k0 + vr)*DH + vc);
        *(float4*)&Vs[vr][vc+4] = *(const float4*)(V + (size_t)(k0 + vr)*DH + vc + 4);
        __syncthreads();
        #pragma unroll 8
        for (int kk = 0; kk < 32; kk++){
            float av[4], bv[8];
            *(float4*)av = *(float4*)&PsT[kk][ty*4];
            *(float4*)&bv[0] = *(float4*)&Vs[kk][tx*8];
            *(float4*)&bv[4] = *(float4*)&Vs[kk][tx*8+4];
            #pragma unroll
            for (int i = 0; i < 4; i++)
                #pragma unroll
                for (int j = 0; j < 8; j++)
                    acc[i][j] = fmaf(av[i], bv[j], acc[i][j]);
        }
        __syncthreads();
    }
    const int b = bh >> 4, h = bh & 15;
    #pragma unroll
    for (int ii = 0; ii < 4; ii++){
        const int i = i0 + ty*4 + ii;
        const float sinv = g_sinv[(size_t)bh*SEQ + i];
        float* orow = g_av + ((size_t)i*BATCH + b)*DM + h*DH + tx*8;
        *(float4*)(orow)     = make_float4(acc[ii][0]*sinv, acc[ii][1]*sinv,
                                           acc[ii][2]*sinv, acc[ii][3]*sinv);
        *(float4*)(orow + 4) = make_float4(acc[ii][4]*sinv, acc[ii][5]*sinv,
                                           acc[ii][6]*sinv, acc[ii][7]*sinv);
    }
}

// ---------------- kernel 5: out projection + residual ----------------
__global__ __launch_bounds__(256) void outproj_kernel(const float* __restrict__ x,
                                                      const float* __restrict__ Wo,
                                                      float* __restrict__ out)
{
    __shared__ float As[16][128];
    __shared__ float Bs[16][128];
    const int m0 = blockIdx.y * 128;
    const int n0 = blockIdx.x * 128;
    const int t = threadIdx.x;
    const int lr = t >> 1;
    const int kh = (t & 1) * 8;
    const int tx = t & 15, ty = t >> 4;

    float acc[8][8];
    #pragma unroll
    for (int i = 0; i < 8; i++)
        #pragma unroll
        for (int j = 0; j < 8; j++) acc[i][j] = 0.f;

    for (int k0 = 0; k0 < DM; k0 += 16){
        #pragma unroll
        for (int q = 0; q < 2; q++){
            const int c = kh + q*4;
            float4 a = *(const float4*)(g_av + (size_t)(m0+lr)*DM + k0 + c);
            As[c+0][lr]=a.x; As[c+1][lr]=a.y; As[c+2][lr]=a.z; As[c+3][lr]=a.w;
            float4 b = *(const float4*)(Wo + (size_t)(n0+lr)*DM + k0 + c);
            Bs[c+0][lr]=b.x; Bs[c+1][lr]=b.y; Bs[c+2][lr]=b.z; Bs[c+3][lr]=b.w;
        }
        __syncthreads();
        #pragma unroll 8
        for (int kk = 0; kk < 16; kk++){
            float av[8], bv[8];
            *(float4*)&av[0] = *(float4*)&As[kk][ty*8];
            *(float4*)&av[4] = *(float4*)&As[kk][ty*8+4];
            *(float4*)&bv[0] = *(float4*)&Bs[kk][tx*8];
            *(float4*)&bv[4] = *(float4*)&Bs[kk][tx*8+4];
            #pragma unroll
            for (int i = 0; i < 8; i++)
                #pragma unroll
                for (int j = 0; j < 8; j++)
                    acc[i][j] = fmaf(av[i], bv[j], acc[i][j]);
        }
        __syncthreads();
    }
    #pragma unroll
    for (int ii = 0; ii < 8; ii++){
        const int m = m0 + ty*8 + ii;
        #pragma unroll
        for (int jh = 0; jh < 2; jh++){
            float4 xr = *(const float4*)(x + (size_t)m*DM + n0 + tx*8 + jh*4);
            float4 o = make_float4(acc[ii][jh*4+0]+xr.x, acc[ii][jh*4+1]+xr.y,
                                   acc[ii][jh*4+2]+xr.z, acc[ii][jh*4+3]+xr.w);
            *(float4*)(out + (size_t)m*DM + n0 + tx*8 + jh*4) = o;
        }
    }
}

// ---------------- kernel 6: LayerNorm ----------------
__global__ __launch_bounds__(256) void ln_kernel(float* __restrict__ out,
                                                 const float* __restrict__ gamma,
                                                 const float* __restrict__ beta)
{
    const int row = blockIdx.x;
    float* y = out + (size_t)row * DM;
    const int t = threadIdx.x;
    float v[4];
    float s = 0.f, sq = 0.f;
    #pragma unroll
    for (int q = 0; q < 4; q++){
        v[q] = y[q*256 + t];
        s += v[q];
        sq += v[q]*v[q];
    }
    __shared__ float sh[16];
    float ws = warpReduceSum(s);
    float wq = warpReduceSum(sq);
    if ((t & 31) == 0){ sh[t>>5] = ws; sh[8 + (t>>5)] = wq; }
    __syncthreads();
    s = 0.f; sq = 0.f;
    #pragma unroll
    for (int w = 0; w < 8; w++){ s += sh[w]; sq += sh[8+w]; }
    const float mu = s * (1.f/1024.f);
    const float var = sq * (1.f/1024.f) - mu*mu;
    const float rstd = rsqrtf(var + 1e-5f);
    #pragma unroll
    for (int q = 0; q < 4; q++){
        const int d = q*256 + t;
        y[d] = gamma[d] * ((v[q] - mu) * rstd) + beta[d];
    }
}

// ---------------- launch ----------------
extern "C" void kernel_launch(void* const* d_in, const int* in_sizes, int n_in,
                              void* d_out, int out_size)
{
    const float* x     = (const float*)d_in[0];
    const float* mem   = (const float*)d_in[1];
    const float* pos   = (const float*)d_in[2];
    const float* pbu   = (const float*)d_in[3];
    const float* pbv   = (const float*)d_in[4];
    const float* Wqkv  = (const float*)d_in[5];
    const float* Wrel  = (const float*)d_in[6];
    const float* Wo    = (const float*)d_in[7];
    const float* gamma = (const float*)d_in[8];
    const float* beta  = (const float*)d_in[9];
    float* out = (float*)d_out;

    static bool attr_set = false;
    if (!attr_set){
        cudaFuncSetAttribute(proj_mma_kernel,
                             cudaFuncAttributeMaxDynamicSharedMemorySize, PJ_SMEM);
        attr_set = true;
    }

    conv_kernel<<<20480, 256>>>(x, mem, pos, Wqkv, Wrel);
    proj_mma_kernel<<<dim3(32, 64), 256, PJ_SMEM>>>(pbu, pbv);
    score_gemm_kernel<<<dim3(16, 8, 128), 256>>>();
    softmax_shift_kernel<<<dim3(1024, 64), 256>>>();
    pv_kernel<<<dim3(8, 64), 256>>>();
    outproj_kernel<<<dim3(8, 32), 256>>>(x, Wo, out);
    ln_kernel<<<4096, 256>>>(out, gamma, beta);
}

// round 5
// speedup vs baseline: 3.1214x; 1.4269x over previous
#include <cuda_runtime.h>
#include <cuda_bf16.h>
#include <math.h>
#include <stdint.h>

#define SEQ   1024
#define MEMN  1024
#define TT    2048
#define BATCH 4
#define NH    16
#define DH    64
#define DM    1024
#define BH    (BATCH*NH)   // 64

// ---------------- scratch (device globals) ----------------
__device__ float g_ac[(size_t)BH*SEQ*TT];     // AC scores fp32
__device__ float g_bd[(size_t)BH*SEQ*TT];     // BD raw fp32

// bf16 hi/lo operands
__device__ __nv_bfloat16 g_chi[(size_t)8192*1024];
__device__ __nv_bfloat16 g_clo[(size_t)8192*1024];
__device__ __nv_bfloat16 g_phi[(size_t)8192*1024];
__device__ __nv_bfloat16 g_plo[(size_t)8192*1024];
__device__ __nv_bfloat16 g_whi[(size_t)4096*1024];
__device__ __nv_bfloat16 g_wlo[(size_t)4096*1024];
__device__ __nv_bfloat16 g_wohi[(size_t)1024*1024];
__device__ __nv_bfloat16 g_wolo[(size_t)1024*1024];

__device__ __nv_bfloat16 g_quh[(size_t)BH*SEQ*DH], g_qul[(size_t)BH*SEQ*DH];
__device__ __nv_bfloat16 g_qvh[(size_t)BH*SEQ*DH], g_qvl[(size_t)BH*SEQ*DH];
__device__ __nv_bfloat16 g_kh [(size_t)BH*TT*DH],  g_kl [(size_t)BH*TT*DH];
__device__ __nv_bfloat16 g_vh [(size_t)BH*TT*DH],  g_vl [(size_t)BH*TT*DH];
__device__ __nv_bfloat16 g_rh [(size_t)BH*TT*DH],  g_rl [(size_t)BH*TT*DH];

__device__ __nv_bfloat16 g_ph[(size_t)BH*SEQ*TT];  // normalized probs hi
__device__ __nv_bfloat16 g_pl[(size_t)BH*SEQ*TT];  // normalized probs lo
__device__ __nv_bfloat16 g_avh[(size_t)SEQ*BATCH*DM], g_avl[(size_t)SEQ*BATCH*DM];

// ---------------- helpers ----------------
__device__ __forceinline__ uint32_t smem_u32(const void* p){
    uint32_t a;
    asm("{ .reg .u64 t; cvta.to.shared.u64 t, %1; cvt.u32.u64 %0, t; }" : "=r"(a) : "l"(p));
    return a;
}
__device__ __forceinline__ void cp16(uint32_t s, const void* g){
    asm volatile("cp.async.cg.shared.global [%0], [%1], 16;" :: "r"(s), "l"(g));
}
#define CP_COMMIT() asm volatile("cp.async.commit_group;" ::: "memory")
#define CP_WAIT0()  asm volatile("cp.async.wait_group 0;" ::: "memory")

__device__ __forceinline__ void ldm4(uint32_t* r, uint32_t addr){
    asm volatile("ldmatrix.sync.aligned.m8n8.x4.shared.b16 {%0,%1,%2,%3}, [%4];"
        : "=r"(r[0]), "=r"(r[1]), "=r"(r[2]), "=r"(r[3]) : "r"(addr));
}
__device__ __forceinline__ void ldm4t(uint32_t* r, uint32_t addr){
    asm volatile("ldmatrix.sync.aligned.m8n8.x4.trans.shared.b16 {%0,%1,%2,%3}, [%4];"
        : "=r"(r[0]), "=r"(r[1]), "=r"(r[2]), "=r"(r[3]) : "r"(addr));
}
__device__ __forceinline__ void mma_bf16(float* c, const uint32_t* a, uint32_t b0, uint32_t b1){
    asm volatile("mma.sync.aligned.m16n8k16.row.col.f32.bf16.bf16.f32 "
        "{%0,%1,%2,%3}, {%4,%5,%6,%7}, {%8,%9}, {%0,%1,%2,%3};"
        : "+f"(c[0]), "+f"(c[1]), "+f"(c[2]), "+f"(c[3])
        : "r"(a[0]), "r"(a[1]), "r"(a[2]), "r"(a[3]), "r"(b0), "r"(b1));
}
__device__ __forceinline__ void split8(const float* v, uint4& hi, uint4& lo){
    uint32_t hs[8], ls[8];
    #pragma unroll
    for (int i = 0; i < 8; i++){
        __nv_bfloat16 h = __float2bfloat16(v[i]);
        hs[i] = __bfloat16_as_ushort(h);
        ls[i] = __bfloat16_as_ushort(__float2bfloat16(v[i] - __bfloat162float(h)));
    }
    hi = make_uint4(hs[0]|(hs[1]<<16), hs[2]|(hs[3]<<16), hs[4]|(hs[5]<<16), hs[6]|(hs[7]<<16));
    lo = make_uint4(ls[0]|(ls[1]<<16), ls[2]|(ls[3]<<16), ls[4]|(ls[5]<<16), ls[6]|(ls[7]<<16));
}

__device__ __forceinline__ float warpReduceSum(float v){
    #pragma unroll
    for (int o = 16; o > 0; o >>= 1) v += __shfl_xor_sync(0xffffffffu, v, o);
    return v;
}
__device__ __forceinline__ float warpReduceMax(float v){
    #pragma unroll
    for (int o = 16; o > 0; o >>= 1) v = fmaxf(v, __shfl_xor_sync(0xffffffffu, v, o));
    return v;
}

// ---------------- kernel 0: fp32 -> bf16 hi/lo conversion prepass ----------------
__global__ __launch_bounds__(256) void conv_kernel(
    const float* __restrict__ x, const float* __restrict__ mem,
    const float* __restrict__ pos, const float* __restrict__ Wqkv,
    const float* __restrict__ Wrel, const float* __restrict__ Wo)
{
    const size_t u = (size_t)blockIdx.x * 256 + threadIdx.x;   // float4 index
    const float* src;
    __nv_bfloat16 *dhi, *dlo;
    size_t elem;
    if (u < 2097152) {                      // c = concat(mem, x)
        elem = u * 4;
        const size_t row = elem >> 10, col = elem & 1023;
        src = (row < 4096) ? (mem + row*1024 + col) : (x + (row-4096)*1024 + col);
        dhi = g_chi + elem; dlo = g_clo + elem;
    } else if (u < 4194304) {               // pos
        elem = (u - 2097152) * 4;
        src = pos + elem;
        dhi = g_phi + elem; dlo = g_plo + elem;
    } else if (u < 5242880) {               // W = concat(Wqkv, Wrel)
        elem = (u - 4194304) * 4;
        const size_t row = elem >> 10, col = elem & 1023;
        src = (row < 3072) ? (Wqkv + row*1024 + col) : (Wrel + (row-3072)*1024 + col);
        dhi = g_whi + elem; dlo = g_wlo + elem;
    } else {                                // Wo
        elem = (u - 5242880) * 4;
        src = Wo + elem;
        dhi = g_wohi + elem; dlo = g_wolo + elem;
    }
    float4 v = *(const float4*)src;
    float vv[8] = {v.x, v.y, v.z, v.w, 0, 0, 0, 0};
    uint32_t hs[4], ls[4];
    #pragma unroll
    for (int i = 0; i < 4; i++){
        __nv_bfloat16 h = __float2bfloat16(vv[i]);
        hs[i] = __bfloat16_as_ushort(h);
        ls[i] = __bfloat16_as_ushort(__float2bfloat16(vv[i] - __bfloat162float(h)));
    }
    *(uint2*)dhi = make_uint2(hs[0]|(hs[1]<<16), hs[2]|(hs[3]<<16));
    *(uint2*)dlo = make_uint2(ls[0]|(ls[1]<<16), ls[2]|(ls[3]<<16));
}

// ---------------- kernel 1: bf16-split projection GEMM via mma.sync ----------------
#define PJ_BUF   40960
#define PJ_SMEM  (2*PJ_BUF)

__global__ __launch_bounds__(256) void proj_mma_kernel(
    const float* __restrict__ pbu, const float* __restrict__ pbv)
{
    extern __shared__ __align__(128) char smem[];
    const uint32_t sbase = smem_u32(smem);
    const int tid = threadIdx.x, lane = tid & 31, wid = tid >> 5;
    const int n0 = blockIdx.x * 128;
    const int m0 = blockIdx.y * 128;
    const bool is_rel = (n0 >= 3072);
    const __nv_bfloat16* Ahp = (is_rel ? g_phi : g_chi) + (size_t)m0 * 1024;
    const __nv_bfloat16* Alp = (is_rel ? g_plo : g_clo) + (size_t)m0 * 1024;
    const __nv_bfloat16* Bhp = g_whi + (size_t)n0 * 1024;
    const __nv_bfloat16* Blp = g_wlo + (size_t)n0 * 1024;

    const int wm = (wid & 3) * 32;
    const int wn = (wid >> 2) * 64;
    const int lsel = lane & 15;
    const int kof  = (lane < 16) ? 0 : 8;

    float acc[2][8][4];
    #pragma unroll
    for (int mt = 0; mt < 2; mt++)
        #pragma unroll
        for (int nt = 0; nt < 8; nt++)
            #pragma unroll
            for (int q = 0; q < 4; q++) acc[mt][nt][q] = 0.f;

    auto issue = [&](int c, int b){
        const int k0 = c * 32;
        const uint32_t sb = sbase + b * PJ_BUF;
        #pragma unroll
        for (int p = 0; p < 2; p++){
            const int u = p * 256 + tid;
            const int row = u >> 2, seg = u & 3;
            const size_t go = (size_t)row * 1024 + k0 + seg * 8;
            const uint32_t so = row * 80 + seg * 16;
            cp16(sb + so,          Ahp + go);
            cp16(sb + 10240 + so,  Alp + go);
            cp16(sb + 20480 + so,  Bhp + go);
            cp16(sb + 30720 + so,  Blp + go);
        }
        CP_COMMIT();
    };

    issue(0, 0);
    for (int c = 0; c < 32; c++){
        CP_WAIT0();
        __syncthreads();
        if (c + 1 < 32) issue(c + 1, (c + 1) & 1);
        const uint32_t sb = sbase + (c & 1) * PJ_BUF;
        #pragma unroll
        for (int kk = 0; kk < 32; kk += 16){
            uint32_t ah[2][4], al[2][4], bh[4][4], bl[4][4];
            #pragma unroll
            for (int mt = 0; mt < 2; mt++){
                const uint32_t ad = sb + (wm + mt*16 + lsel) * 80 + (kk + kof) * 2;
                ldm4(ah[mt], ad);
                ldm4(al[mt], ad + 10240);
            }
            #pragma unroll
            for (int g = 0; g < 4; g++){
                const uint32_t bd = sb + 20480 + (wn + g*16 + lsel) * 80 + (kk + kof) * 2;
                ldm4(bh[g], bd);
                ldm4(bl[g], bd + 10240);
            }
            #pragma unroll
            for (int mt = 0; mt < 2; mt++)
                #pragma unroll
                for (int nt = 0; nt < 8; nt++){
                    const int g = nt >> 1, s = nt & 1;
                    mma_bf16(acc[mt][nt], ah[mt], bh[g][s], bh[g][s+2]);
                    mma_bf16(acc[mt][nt], ah[mt], bl[g][s], bl[g][s+2]);
                    mma_bf16(acc[mt][nt], al[mt], bh[g][s], bh[g][s+2]);
                }
        }
    }

    // epilogue: stage fp32, then split to bf16 hi/lo head-major outputs
    __syncthreads();
    float* stg = (float*)smem;
    const int fr = lane >> 2, fc = (lane & 3) * 2;
    #pragma unroll
    for (int mt = 0; mt < 2; mt++)
        #pragma unroll
        for (int nt = 0; nt < 8; nt++){
            const int col = wn + nt*8 + fc;
            const int row0 = wm + mt*16 + fr;
            stg[row0*132 + col]       = acc[mt][nt][0];
            stg[row0*132 + col + 1]   = acc[mt][nt][1];
            stg[(row0+8)*132 + col]   = acc[mt][nt][2];
            stg[(row0+8)*132 + col+1] = acc[mt][nt][3];
        }
    __syncthreads();

    const int rr = tid >> 1, hf = tid & 1;
    const int m = m0 + rr;
    const int t_ = m >> 2, b_ = m & 3;
    const float* src = stg + rr * 132 + hf * 64;
    const int nbase = n0 + hf * 64;
    const int cat = n0 >> 10;             // 0=q 1=k 2=v 3=r
    if (cat == 0){
        if (t_ >= MEMN){
            const int i = t_ - MEMN;
            const int h = nbase >> 6;
            const size_t off = (((size_t)(b_*NH + h))*SEQ + i)*DH;
            #pragma unroll
            for (int s = 0; s < 8; s++){
                float qu8[8], qv8[8];
                #pragma unroll
                for (int e = 0; e < 8; e++){
                    const float v = src[s*8 + e];
                    qu8[e] = v + pbu[nbase + s*8 + e];
                    qv8[e] = v + pbv[nbase + s*8 + e];
                }
                uint4 hi, lo;
                split8(qu8, hi, lo);
                *(uint4*)(g_quh + off + s*8) = hi;
                *(uint4*)(g_qul + off + s*8) = lo;
                split8(qv8, hi, lo);
                *(uint4*)(g_qvh + off + s*8) = hi;
                *(uint4*)(g_qvl + off + s*8) = lo;
            }
        }
    } else {
        const int nn = nbase - cat*1024;
        const int h = nn >> 6;
        __nv_bfloat16* bh_ = (cat == 1) ? g_kh : (cat == 2) ? g_vh : g_rh;
        __nv_bfloat16* bl_ = (cat == 1) ? g_kl : (cat == 2) ? g_vl : g_rl;
        const size_t off = (((size_t)(b_*NH + h))*TT + t_)*DH;
        #pragma unroll
        for (int s = 0; s < 8; s++){
            uint4 hi, lo;
            split8(src + s*8, hi, lo);
            *(uint4*)(bh_ + off + s*8) = hi;
            *(uint4*)(bl_ + off + s*8) = lo;
        }
    }
}

// ---------------- kernel 2: bf16-split score GEMMs (K=64) ----------------
// z = bh*2+which; AC = qu@k^T or BDraw = qv@r^T; 128x128 tile; fp32 out.
#define SC_SMEM 73728

__global__ __launch_bounds__(256) void score_mma_kernel()
{
    extern __shared__ __align__(128) char smem[];
    const uint32_t sbase = smem_u32(smem);
    const int tid = threadIdx.x, lane = tid & 31, wid = tid >> 5;
    const int z = blockIdx.z;
    const int bh = z >> 1, which = z & 1;
    const __nv_bfloat16* Ahp = (which ? g_qvh : g_quh) + (size_t)bh * SEQ * DH;
    const __nv_bfloat16* Alp = (which ? g_qvl : g_qul) + (size_t)bh * SEQ * DH;
    const __nv_bfloat16* Bhp = (which ? g_rh  : g_kh ) + (size_t)bh * TT  * DH;
    const __nv_bfloat16* Blp = (which ? g_rl  : g_kl ) + (size_t)bh * TT  * DH;
    float* Ob = (which ? g_bd : g_ac) + (size_t)bh * SEQ * TT;
    const int i0 = blockIdx.y * 128;
    const int j0 = blockIdx.x * 128;

    const int wm = (wid & 3) * 32;
    const int wn = (wid >> 2) * 64;
    const int lsel = lane & 15;
    const int kof  = (lane < 16) ? 0 : 8;

    // load full K=64 tiles: Ah@0 Al@18432 Bh@36864 Bl@55296, stride 144B
    #pragma unroll
    for (int p = 0; p < 4; p++){
        const int u = p * 256 + tid;
        const int row = u >> 3, seg = u & 7;
        const uint32_t so = row * 144 + seg * 16;
        const size_t goA = (size_t)(i0 + row) * DH + seg * 8;
        const size_t goB = (size_t)(j0 + row) * DH + seg * 8;
        cp16(sbase + so,          Ahp + goA);
        cp16(sbase + 18432 + so,  Alp + goA);
        cp16(sbase + 36864 + so,  Bhp + goB);
        cp16(sbase + 55296 + so,  Blp + goB);
    }
    CP_COMMIT();

    float acc[2][8][4];
    #pragma unroll
    for (int mt = 0; mt < 2; mt++)
        #pragma unroll
        for (int nt = 0; nt < 8; nt++)
            #pragma unroll
            for (int q = 0; q < 4; q++) acc[mt][nt][q] = 0.f;

    CP_WAIT0();
    __syncthreads();

    #pragma unroll
    for (int kk = 0; kk < 64; kk += 16){
        uint32_t ah[2][4], al[2][4], bh[4][4], bl[4][4];
        #pragma unroll
        for (int mt = 0; mt < 2; mt++){
            const uint32_t ad = sbase + (wm + mt*16 + lsel) * 144 + (kk + kof) * 2;
            ldm4(ah[mt], ad);
            ldm4(al[mt], ad + 18432);
        }
        #pragma unroll
        for (int g = 0; g < 4; g++){
            const uint32_t bd = sbase + 36864 + (wn + g*16 + lsel) * 144 + (kk + kof) * 2;
            ldm4(bh[g], bd);
            ldm4(bl[g], bd + 18432);
        }
        #pragma unroll
        for (int mt = 0; mt < 2; mt++)
            #pragma unroll
            for (int nt = 0; nt < 8; nt++){
                const int g = nt >> 1, s = nt & 1;
                mma_bf16(acc[mt][nt], ah[mt], bh[g][s], bh[g][s+2]);
                mma_bf16(acc[mt][nt], ah[mt], bl[g][s], bl[g][s+2]);
                mma_bf16(acc[mt][nt], al[mt], bh[g][s], bh[g][s+2]);
            }
    }

    // stage + coalesced fp32 write
    __syncthreads();
    float* stg = (float*)smem;
    const int fr = lane >> 2, fc = (lane & 3) * 2;
    #pragma unroll
    for (int mt = 0; mt < 2; mt++)
        #pragma unroll
        for (int nt = 0; nt < 8; nt++){
            const int col = wn + nt*8 + fc;
            const int row0 = wm + mt*16 + fr;
            stg[row0*132 + col]       = acc[mt][nt][0];
            stg[row0*132 + col + 1]   = acc[mt][nt][1];
            stg[(row0+8)*132 + col]   = acc[mt][nt][2];
            stg[(row0+8)*132 + col+1] = acc[mt][nt][3];
        }
    __syncthreads();
    const int rr = tid >> 1, hf = tid & 1;
    const float* src = stg + rr * 132 + hf * 64;
    float* orow = Ob + (size_t)(i0 + rr) * TT + j0 + hf * 64;
    #pragma unroll
    for (int s = 0; s < 16; s++)
        *(float4*)(orow + s*4) = *(const float4*)(src + s*4);
}

// ---------------- kernel 3: rel-shift + softmax -> normalized bf16 hi/lo probs ----------------
__global__ __launch_bounds__(256) void softmax_shift_kernel()
{
    const int i  = blockIdx.x;
    const int bh = blockIdx.y;
    const int t  = threadIdx.x;
    const size_t rowoff = ((size_t)bh*SEQ + i) * TT;
    const float* ac = g_ac + rowoff;
    const float* bd0 = g_bd + rowoff;
    const float* bd1 = bd0 + TT;

    float sv[8];
    float lmax = -INFINITY;
    #pragma unroll
    for (int q = 0; q < 8; q++){
        const int j = q*256 + t;
        const int delta = j - i;
        float bd;
        if (delta <= 1024)      bd = bd0[delta + 1023];
        else if (delta == 1025) bd = 0.f;
        else                    bd = bd1[delta - 1026];
        const float s = (ac[j] + bd) * 0.125f;
        sv[q] = s;
        lmax = fmaxf(lmax, s);
    }
    __shared__ float sh[8];
    float wmax = warpReduceMax(lmax);
    if ((t & 31) == 0) sh[t >> 5] = wmax;
    __syncthreads();
    float mx = sh[0];
    #pragma unroll
    for (int w = 1; w < 8; w++) mx = fmaxf(mx, sh[w]);
    __syncthreads();

    float lsum = 0.f;
    #pragma unroll
    for (int q = 0; q < 8; q++){
        const float p = __expf(sv[q] - mx);
        sv[q] = p;
        lsum += p;
    }
    float wsum = warpReduceSum(lsum);
    if ((t & 31) == 0) sh[t >> 5] = wsum;
    __syncthreads();
    float sum = 0.f;
    #pragma unroll
    for (int w = 0; w < 8; w++) sum += sh[w];
    const float sinv = 1.f / sum;

    __nv_bfloat16* ph = g_ph + rowoff;
    __nv_bfloat16* pl = g_pl + rowoff;
    #pragma unroll
    for (int q = 0; q < 8; q++){
        const int j = q*256 + t;
        const float pn = sv[q] * sinv;
        const __nv_bfloat16 h = __float2bfloat16(pn);
        ph[j] = h;
        pl[j] = __float2bfloat16(pn - __bfloat162float(h));
    }
}

// ---------------- kernel 4: bf16-split PV GEMM ----------------
// C[128 x 64] tiles: P [i][j] (normal ldmatrix) x V [j][d] (trans ldmatrix), K=2048.
#define PV_BUF   29696
#define PV_SMEM  (2*PV_BUF)

__global__ __launch_bounds__(256) void pv_mma_kernel()
{
    extern __shared__ __align__(128) char smem[];
    const uint32_t sbase = smem_u32(smem);
    const int tid = threadIdx.x, lane = tid & 31, wid = tid >> 5;
    const int bh = blockIdx.y;
    const int i0 = blockIdx.x * 128;
    const __nv_bfloat16* Php = g_ph + (size_t)bh*SEQ*TT + (size_t)i0*TT;
    const __nv_bfloat16* Plp = g_pl + (size_t)bh*SEQ*TT + (size_t)i0*TT;
    const __nv_bfloat16* Vhp = g_vh + (size_t)bh*TT*DH;
    const __nv_bfloat16* Vlp = g_vl + (size_t)bh*TT*DH;

    const int wm = (wid & 3) * 32;
    const int wn = (wid >> 2) * 32;
    const int lsel = lane & 15;
    const int kof  = (lane < 16) ? 0 : 8;
    const int tcol = (lane >> 4) * 8;      // for trans ldmatrix

    float acc[2][4][4];
    #pragma unroll
    for (int mt = 0; mt < 2; mt++)
        #pragma unroll
        for (int nt = 0; nt < 4; nt++)
            #pragma unroll
            for (int q = 0; q < 4; q++) acc[mt][nt][q] = 0.f;

    auto issue = [&](int c, int b){
        const int k0 = c * 32;
        const uint32_t sb = sbase + b * PV_BUF;
        // P: 128 rows x 32 bf16, stride 80B; hi @0, lo @10240
        #pragma unroll
        for (int p = 0; p < 2; p++){
            const int u = p * 256 + tid;
            const int row = u >> 2, seg = u & 3;
            const size_t go = (size_t)row * TT + k0 + seg * 8;
            const uint32_t so = row * 80 + seg * 16;
            cp16(sb + so,         Php + go);
            cp16(sb + 10240 + so, Plp + go);
        }
        // V: 32 rows x 64 bf16, stride 144B; hi @20480, lo @25088
        {
            const int row = tid >> 3, seg = tid & 7;
            const size_t go = (size_t)(k0 + row) * DH + seg * 8;
            const uint32_t so = row * 144 + seg * 16;
            cp16(sb + 20480 + so, Vhp + go);
            cp16(sb + 25088 + so, Vlp + go);
        }
        CP_COMMIT();
    };

    issue(0, 0);
    for (int c = 0; c < 64; c++){
        CP_WAIT0();
        __syncthreads();
        if (c + 1 < 64) issue(c + 1, (c + 1) & 1);
        const uint32_t sb = sbase + (c & 1) * PV_BUF;
        #pragma unroll
        for (int kk = 0; kk < 32; kk += 16){
            uint32_t ph[2][4], pl[2][4], vh[2][4], vl[2][4];
            #pragma unroll
            for (int mt = 0; mt < 2; mt++){
                const uint32_t ad = sb + (wm + mt*16 + lsel) * 80 + (kk + kof) * 2;
                ldm4(ph[mt], ad);
                ldm4(pl[mt], ad + 10240);
            }
            #pragma unroll
            for (int g = 0; g < 2; g++){
                const uint32_t bd = sb + 20480 + (kk + lsel) * 144 + (wn + g*16 + tcol) * 2;
                ldm4t(vh[g], bd);
                ldm4t(vl[g], bd + 4608);
            }
            #pragma unroll
            for (int mt = 0; mt < 2; mt++)
                #pragma unroll
                for (int nt = 0; nt < 4; nt++){
                    const int g = nt >> 1, s = nt & 1;
                    mma_bf16(acc[mt][nt], ph[mt], vh[g][2*s], vh[g][2*s+1]);
                    mma_bf16(acc[mt][nt], ph[mt], vl[g][2*s], vl[g][2*s+1]);
                    mma_bf16(acc[mt][nt], pl[mt], vh[g][2*s], vh[g][2*s+1]);
                }
        }
    }

    // stage + split to g_avh/g_avl
    __syncthreads();
    float* stg = (float*)smem;
    const int fr = lane >> 2, fc = (lane & 3) * 2;
    #pragma unroll
    for (int mt = 0; mt < 2; mt++)
        #pragma unroll
        for (int nt = 0; nt < 4; nt++){
            const int col = wn + nt*8 + fc;
            const int row0 = wm + mt*16 + fr;
            stg[row0*68 + col]       = acc[mt][nt][0];
            stg[row0*68 + col + 1]   = acc[mt][nt][1];
            stg[(row0+8)*68 + col]   = acc[mt][nt][2];
            stg[(row0+8)*68 + col+1] = acc[mt][nt][3];
        }
    __syncthreads();
    const int rr = tid >> 1, hf = tid & 1;
    const int b = bh >> 4, h = bh & 15;
    const int i = i0 + rr;
    const float* src = stg + rr * 68 + hf * 32;
    const size_t off = ((size_t)i*BATCH + b)*DM + h*DH + hf*32;
    #pragma unroll
    for (int s = 0; s < 4; s++){
        uint4 hi, lo;
        split8(src + s*8, hi, lo);
        *(uint4*)(g_avh + off + s*8) = hi;
        *(uint4*)(g_avl + off + s*8) = lo;
    }
}

// ---------------- kernel 5: bf16-split out projection + residual ----------------
__global__ __launch_bounds__(256) void outproj_mma_kernel(const float* __restrict__ x,
                                                          float* __restrict__ out)
{
    extern __shared__ __align__(128) char smem[];
    const uint32_t sbase = smem_u32(smem);
    const int tid = threadIdx.x, lane = tid & 31, wid = tid >> 5;
    const int n0 = blockIdx.x * 128;
    const int m0 = blockIdx.y * 128;
    const __nv_bfloat16* Ahp = g_avh + (size_t)m0 * 1024;
    const __nv_bfloat16* Alp = g_avl + (size_t)m0 * 1024;
    const __nv_bfloat16* Bhp = g_wohi + (size_t)n0 * 1024;
    const __nv_bfloat16* Blp = g_wolo + (size_t)n0 * 1024;

    const int wm = (wid & 3) * 32;
    const int wn = (wid >> 2) * 64;
    const int lsel = lane & 15;
    const int kof  = (lane < 16) ? 0 : 8;

    float acc[2][8][4];
    #pragma unroll
    for (int mt = 0; mt < 2; mt++)
        #pragma unroll
        for (int nt = 0; nt < 8; nt++)
            #pragma unroll
            for (int q = 0; q < 4; q++) acc[mt][nt][q] = 0.f;

    auto issue = [&](int c, int b){
        const int k0 = c * 32;
        const uint32_t sb = sbase + b * PJ_BUF;
        #pragma unroll
        for (int p = 0; p < 2; p++){
            const int u = p * 256 + tid;
            const int row = u >> 2, seg = u & 3;
            const size_t go = (size_t)row * 1024 + k0 + seg * 8;
            const uint32_t so = row * 80 + seg * 16;
            cp16(sb + so,          Ahp + go);
            cp16(sb + 10240 + so,  Alp + go);
            cp16(sb + 20480 + so,  Bhp + go);
            cp16(sb + 30720 + so,  Blp + go);
        }
        CP_COMMIT();
    };

    issue(0, 0);
    for (int c = 0; c < 32; c++){
        CP_WAIT0();
        __syncthreads();
        if (c + 1 < 32) issue(c + 1, (c + 1) & 1);
        const uint32_t sb = sbase + (c & 1) * PJ_BUF;
        #pragma unroll
        for (int kk = 0; kk < 32; kk += 16){
            uint32_t ah[2][4], al[2][4], bh[4][4], bl[4][4];
            #pragma unroll
            for (int mt = 0; mt < 2; mt++){
                const uint32_t ad = sb + (wm + mt*16 + lsel) * 80 + (kk + kof) * 2;
                ldm4(ah[mt], ad);
                ldm4(al[mt], ad + 10240);
            }
            #pragma unroll
            for (int g = 0; g < 4; g++){
                const uint32_t bd = sb + 20480 + (wn + g*16 + lsel) * 80 + (kk + kof) * 2;
                ldm4(bh[g], bd);
                ldm4(bl[g], bd + 10240);
            }
            #pragma unroll
            for (int mt = 0; mt < 2; mt++)
                #pragma unroll
                for (int nt = 0; nt < 8; nt++){
                    const int g = nt >> 1, s = nt & 1;
                    mma_bf16(acc[mt][nt], ah[mt], bh[g][s], bh[g][s+2]);
                    mma_bf16(acc[mt][nt], ah[mt], bl[g][s], bl[g][s+2]);
                    mma_bf16(acc[mt][nt], al[mt], bh[g][s], bh[g][s+2]);
                }
        }
    }

    __syncthreads();
    float* stg = (float*)smem;
    const int fr = lane >> 2, fc = (lane & 3) * 2;
    #pragma unroll
    for (int mt = 0; mt < 2; mt++)
        #pragma unroll
        for (int nt = 0; nt < 8; nt++){
            const int col = wn + nt*8 + fc;
            const int row0 = wm + mt*16 + fr;
            stg[row0*132 + col]       = acc[mt][nt][0];
            stg[row0*132 + col + 1]   = acc[mt][nt][1];
            stg[(row0+8)*132 + col]   = acc[mt][nt][2];
            stg[(row0+8)*132 + col+1] = acc[mt][nt][3];
        }
    __syncthreads();
    const int rr = tid >> 1, hf = tid & 1;
    const int m = m0 + rr;
    const float* src = stg + rr * 132 + hf * 64;
    const float* xr = x + (size_t)m*DM + n0 + hf*64;
    float* orow = out + (size_t)m*DM + n0 + hf*64;
    #pragma unroll
    for (int s = 0; s < 16; s++){
        float4 v = *(const float4*)(src + s*4);
        float4 xx = *(const float4*)(xr + s*4);
        *(float4*)(orow + s*4) = make_float4(v.x+xx.x, v.y+xx.y, v.z+xx.z, v.w+xx.w);
    }
}

// ---------------- kernel 6: LayerNorm ----------------
__global__ __launch_bounds__(256) void ln_kernel(float* __restrict__ out,
                                                 const float* __restrict__ gamma,
                                                 const float* __restrict__ beta)
{
    const int row = blockIdx.x;
    float* y = out + (size_t)row * DM;
    const int t = threadIdx.x;
    float v[4];
    float s = 0.f, sq = 0.f;
    #pragma unroll
    for (int q = 0; q < 4; q++){
        v[q] = y[q*256 + t];
        s += v[q];
        sq += v[q]*v[q];
    }
    __shared__ float sh[16];
    float ws = warpReduceSum(s);
    float wq = warpReduceSum(sq);
    if ((t & 31) == 0){ sh[t>>5] = ws; sh[8 + (t>>5)] = wq; }
    __syncthreads();
    s = 0.f; sq = 0.f;
    #pragma unroll
    for (int w = 0; w < 8; w++){ s += sh[w]; sq += sh[8+w]; }
    const float mu = s * (1.f/1024.f);
    const float var = sq * (1.f/1024.f) - mu*mu;
    const float rstd = rsqrtf(var + 1e-5f);
    #pragma unroll
    for (int q = 0; q < 4; q++){
        const int d = q*256 + t;
        y[d] = gamma[d] * ((v[q] - mu) * rstd) + beta[d];
    }
}

// ---------------- launch ----------------
extern "C" void kernel_launch(void* const* d_in, const int* in_sizes, int n_in,
                              void* d_out, int out_size)
{
    const float* x     = (const float*)d_in[0];
    const float* mem   = (const float*)d_in[1];
    const float* pos   = (const float*)d_in[2];
    const float* pbu   = (const float*)d_in[3];
    const float* pbv   = (const float*)d_in[4];
    const float* Wqkv  = (const float*)d_in[5];
    const float* Wrel  = (const float*)d_in[6];
    const float* Wo    = (const float*)d_in[7];
    const float* gamma = (const float*)d_in[8];
    const float* beta  = (const float*)d_in[9];
    float* out = (float*)d_out;

    static bool attr_set = false;
    if (!attr_set){
        cudaFuncSetAttribute(proj_mma_kernel,    cudaFuncAttributeMaxDynamicSharedMemorySize, PJ_SMEM);
        cudaFuncSetAttribute(score_mma_kernel,   cudaFuncAttributeMaxDynamicSharedMemorySize, SC_SMEM);
        cudaFuncSetAttribute(pv_mma_kernel,      cudaFuncAttributeMaxDynamicSharedMemorySize, PV_SMEM);
        cudaFuncSetAttribute(outproj_mma_kernel, cudaFuncAttributeMaxDynamicSharedMemorySize, PJ_SMEM);
        attr_set = true;
    }

    conv_kernel<<<21504, 256>>>(x, mem, pos, Wqkv, Wrel, Wo);
    proj_mma_kernel<<<dim3(32, 64), 256, PJ_SMEM>>>(pbu, pbv);
    score_mma_kernel<<<dim3(16, 8, 128), 256, SC_SMEM>>>();
    softmax_shift_kernel<<<dim3(1024, 64), 256>>>();
    pv_mma_kernel<<<dim3(8, 64), 256, PV_SMEM>>>();
    outproj_mma_kernel<<<dim3(8, 32), 256, PJ_SMEM>>>(x, out);
    ln_kernel<<<4096, 256>>>(out, gamma, beta);
}